// round 7
// baseline (speedup 1.0000x reference)
#include <cuda_runtime.h>

#define BB 256
#define AA 128
#define DD 5
#define FATOM 256
#define FBOND 64
#define FTOT 320   // FATOM + FBOND
#define CC 256
#define NROWS (BB * AA)
#define TILE_M 16
#define TILES_X 80

typedef unsigned long long ull;

// Scratch (no device allocation allowed anywhere).
__device__ int g_count[DD];
__device__ int g_rows[DD * NROWS];

// ---------------- packed f32x2 helpers ----------------
__device__ __forceinline__ ull fma2(ull a, ull b, ull c) {
    ull d;
    asm("fma.rn.f32x2 %0, %1, %2, %3;" : "=l"(d) : "l"(a), "l"(b), "l"(c));
    return d;
}
__device__ __forceinline__ void unpack2(ull v, float& lo, float& hi) {
    asm("mov.b64 {%0, %1}, %2;" : "=f"(lo), "=f"(hi) : "l"(v));
}
__device__ __forceinline__ ull pack2(float lo, float hi) {
    ull r;
    asm("mov.b64 %0, {%1, %2};" : "=l"(r) : "f"(lo), "f"(hi));
    return r;
}
// 16B smem load: two packed (v,v) f32x2 operands (feat[f], feat[f+1])
__device__ __forceinline__ void lds_v2u64(ull& a, ull& b, unsigned saddr) {
    asm volatile("ld.shared.v2.u64 {%0, %1}, [%2];"
                 : "=l"(a), "=l"(b) : "r"(saddr));
}

// Kernel A (fused): per-row degree; deg==5 rows -> zero output row;
// deg<5 rows -> append to deg-list. Warp handles 4 rows via ballot.
// Append order varies but each row handled exactly once -> deterministic.
__global__ void __launch_bounds__(256) classify_zero_kernel(
    const int* __restrict__ edges, float4* __restrict__ out4)
{
    const int wid  = threadIdx.x >> 5;
    const int lane = threadIdx.x & 31;
    const int rbase = blockIdx.x * 32 + wid * 4;
    const float4 z = make_float4(0.f, 0.f, 0.f, 0.f);

#pragma unroll
    for (int i = 0; i < 4; i++) {
        const int row = rbase + i;
        int e = -1;
        if (lane < DD) e = edges[row * DD + lane];
        unsigned m = __ballot_sync(0xffffffffu, (lane < DD) && (e >= 0));
        int deg = __popc(m);
        if (deg == DD) {
            float4* o = out4 + row * (CC / 4);
            o[lane] = z;
            o[lane + 32] = z;
        } else if (lane == 0) {
            int pos = atomicAdd(&g_count[deg], 1);
            g_rows[deg * NROWS + pos] = row;
        }
    }
}

// Kernel B: per-deg grouped GEMM (simple, latency-tolerant form).
// Tile = 16 rows x 256 cols, 256 threads: cp = tid&127 -> cols 2cp,2cp+1;
// rg = tid>>7 -> rows rg*8..rg*8+7. feat stored DUPLICATED ((v,v) u64) so
// fma.rn.f32x2 operands come straight from broadcast ld.shared.v2.u64 with
// zero packing movs. W read directly (LDG.64, coalesced, L2-resident),
// f-unrolled x4 for MLP. One barrier pair per tile.
__global__ void __launch_bounds__(256) gemm_kernel(
    const float4* __restrict__ atoms4, const float4* __restrict__ bonds4,
    const int* __restrict__ edges, const float* __restrict__ W,
    const float* __restrict__ bias, float* __restrict__ out)
{
    __shared__ ull featd[TILE_M][FTOT];   // duplicated feat: 40 KB

    const int deg = blockIdx.y;
    const int count = g_count[deg];
    if (count == 0) return;

    const int tid  = threadIdx.x;
    const int wid  = tid >> 5;
    const int lane = tid & 31;
    const int cp   = tid & 127;   // cols 2cp, 2cp+1
    const int rg   = tid >> 7;    // rows rg*8 .. rg*8+7
    const ull* Wp = reinterpret_cast<const ull*>(W + deg * FTOT * CC) + cp;
    const ull bv2 =
        *reinterpret_cast<const ull*>(&bias[deg * CC + 2 * cp]);

    // smem byte bases for this thread's 8 feat rows
    unsigned fb[8];
#pragma unroll
    for (int r = 0; r < 8; r++)
        fb[r] = (unsigned)__cvta_generic_to_shared(&featd[rg * 8 + r][0]);

    for (int tile = blockIdx.x; tile * TILE_M < count; tile += gridDim.x) {
        const int base  = tile * TILE_M;
        const int nrows = min(TILE_M, count - base);

        __syncthreads();  // prior-iteration feat readers done

        // ---- Feat build (duplicated): warp wid builds rows wid, wid+8 ----
#pragma unroll
        for (int rr = 0; rr < 2; rr++) {
            const int r = wid + rr * 8;
            if (r < nrows) {
                const int row   = g_rows[deg * NROWS + base + r];
                const int bbase = (row >> 7) << 7;  // b * AA
                int e[DD];
#pragma unroll
                for (int d = 0; d < DD; d++) e[d] = edges[row * DD + d];
#pragma unroll
                for (int k = 0; k < 2; k++) {
                    const int f4 = lane + 32 * k;      // float4 idx (f = 4*f4)
                    float4 v = atoms4[row * 64 + f4];
#pragma unroll
                    for (int d = 0; d < DD; d++) {
                        if (e[d] >= 0) {
                            float4 nv = atoms4[(bbase + e[d]) * 64 + f4];
                            v.x += nv.x; v.y += nv.y; v.z += nv.z; v.w += nv.w;
                        }
                    }
                    float4* dst = reinterpret_cast<float4*>(&featd[r][4 * f4]);
                    dst[0] = make_float4(v.x, v.x, v.y, v.y);
                    dst[1] = make_float4(v.z, v.z, v.w, v.w);
                }
                if (lane < 16) {
                    float4 s = make_float4(0.f, 0.f, 0.f, 0.f);
#pragma unroll
                    for (int d = 0; d < DD; d++) {
                        float4 bvv = bonds4[(row * DD + d) * 16 + lane];
                        s.x += bvv.x; s.y += bvv.y; s.z += bvv.z; s.w += bvv.w;
                    }
                    float4* dst = reinterpret_cast<float4*>(&featd[r][FATOM + 4 * lane]);
                    dst[0] = make_float4(s.x, s.x, s.y, s.y);
                    dst[1] = make_float4(s.z, s.z, s.w, s.w);
                }
            }
        }
        __syncthreads();

        // ---- GEMM: 8 rows x 2 cols per thread, W direct from L2 ----
        ull acc[8];
#pragma unroll
        for (int r = 0; r < 8; r++) acc[r] = bv2;

        const ull* wp = Wp;
        for (int f = 0; f < FTOT; f += 4) {
            // 4 independent W loads up front (MLP=4)
            const ull w0 = wp[0 * (CC / 2)];
            const ull w1 = wp[1 * (CC / 2)];
            const ull w2 = wp[2 * (CC / 2)];
            const ull w3 = wp[3 * (CC / 2)];
            wp += 4 * (CC / 2);
            const unsigned fo = f * 8;   // byte offset into featd row
#pragma unroll
            for (int r = 0; r < 8; r++) {
                ull p0, p1, p2, p3;
                lds_v2u64(p0, p1, fb[r] + fo);        // feat f, f+1 (dup-packed)
                lds_v2u64(p2, p3, fb[r] + fo + 16);   // feat f+2, f+3
                acc[r] = fma2(p0, w0, acc[r]);
                acc[r] = fma2(p1, w1, acc[r]);
                acc[r] = fma2(p2, w2, acc[r]);
                acc[r] = fma2(p3, w3, acc[r]);
            }
        }

        // ---- Epilogue: relu + float2 store per row ----
#pragma unroll
        for (int r = 0; r < 8; r++) {
            const int ri = rg * 8 + r;
            if (ri < nrows) {
                const int row = g_rows[deg * NROWS + base + ri];
                float lo, hi;
                unpack2(acc[r], lo, hi);
                float2 o = make_float2(fmaxf(lo, 0.f), fmaxf(hi, 0.f));
                *reinterpret_cast<float2*>(&out[row * CC + 2 * cp]) = o;
            }
        }
    }
}

extern "C" void kernel_launch(void* const* d_in, const int* in_sizes, int n_in,
                              void* d_out, int out_size) {
    const float* atoms = (const float*)d_in[0];   // (B, A, FA) f32
    const float* bonds = (const float*)d_in[1];   // (B, A, D, FB) f32
    const int*   edges = (const int*)d_in[2];     // (B, A, D) i32
    const float* W     = (const float*)d_in[3];   // (D, FA+FB, C) f32
    const float* bias  = (const float*)d_in[4];   // (D, C) f32
    float* out = (float*)d_out;                   // (B, A, C) f32

    // Reset compaction counters (memset node; no allocation).
    void* cnt_addr = nullptr;
    cudaGetSymbolAddress(&cnt_addr, g_count);
    cudaMemsetAsync(cnt_addr, 0, DD * sizeof(int));

    classify_zero_kernel<<<NROWS / 32, 256>>>(edges, (float4*)out);
    // grid: x = tile slots (stride loop), y = deg
    gemm_kernel<<<dim3(TILES_X, DD), 256>>>((const float4*)atoms,
                                            (const float4*)bonds,
                                            edges, W, bias, out);
}